// round 8
// baseline (speedup 1.0000x reference)
#include <cuda_runtime.h>
#include <cuda_fp16.h>

// Problem constants
#define NC     5
#define NB     128000
#define BATCH  8
#define NJ     15
#define HH     128
#define WW     240
#define HMPIX  (HH*WW)        // 30720 pixels per (b,cam,j) heatmap

// Tiling: 1024 threads (32 warps). smem 123.8KB forces 1 CTA/SM.
#define THREADS 1024
#define BPT     25            // bins per thread, full task
#define MBPT    5             // bins per thread, mini task
#define CHUNK   (THREADS*BPT) // 25600 bins per full task
#define MCHUNK  (THREADS*MBPT)// 5120 bins per mini task
// 600 logical chunks (5 per (b,j) x 120). Tail-wave fix: the last 8 chunks
// (ids 592..599) are split into 5 minis each -> 592 + 40 = 632 CTAs.
// Full tasks dispatch first; the 40 minis dispatch last and fill the tail
// wave across 40 SMs in parallel instead of 8 SMs running full chunks.
#define NFULL   592
#define NMINI   40
#define NTASK   (NFULL + NMINI)

// Fused 8-byte per-(cam,bin) record (shared across all b,j):
//   .x = off (bits 0..15) | t_half_bits (bits 16..31)
//   .y = half2(vA, vB)
// Semantics: result = (vA,vB) . ( p0 + t*(p1-p0) )
// p0 = pair at off (row y0), p1 = pair at off+WW (smem row 128 is zero pad).
// Border (zeros-padding) cases folded into (vA, vB, t) by prep.
__device__ uint2 g_rec[NC*NB];

__global__ void prep_kernel(const float* __restrict__ grid) {
    int idx = blockIdx.x * 256 + threadIdx.x;
    if (idx >= NC*NB) return;
    float2 g = reinterpret_cast<const float2*>(grid)[idx];

    // align_corners=True mapping
    float ix = (g.x + 1.0f) * 0.5f * (float)(WW - 1);
    float iy = (g.y + 1.0f) * 0.5f * (float)(HH - 1);
    float x0f = floorf(ix), y0f = floorf(iy);
    float fx = ix - x0f,    fy = iy - y0f;
    int   x0 = (int)x0f,    y0 = (int)y0f;

    // x: pair at xc provides (hm[y][xc], hm[y][xc+1]); fill zero-pads the
    // second element at xc==WW-1, so invalid x1 contributes 0.
    float wA, wB; int xc;
    if (x0 >= 0 && x0 < WW) { xc = x0; wA = 1.0f - fx; wB = fx;  }
    else if (x0 == -1)      { xc = 0;  wA = fx;        wB = 0.f; }
    else                    { xc = 0;  wA = 0.f;       wB = 0.f; }

    // y folded into (t, s): interior t=fy,s=1 (pad row zero handles y0=127);
    // y0==-1: use row 0 only, s=fy; fully OOB: s=0.
    float t, s; int yc;
    if (y0 >= 0 && y0 < HH) { yc = y0; t = fy;  s = 1.f; }
    else if (y0 == -1)      { yc = 0;  t = 0.f; s = fy;  }
    else                    { yc = 0;  t = 0.f; s = 0.f; }

    unsigned int off = (unsigned int)(yc * WW + xc);   // <= 30719, 15 bits
    __half th = __float2half_rn(t);
    __half2 v = __floats2half2_rn(wA * s, wB * s);

    uint2 r;
    r.x = off | ((unsigned int)__half_as_ushort(th) << 16);
    r.y = *reinterpret_cast<unsigned int*>(&v);
    g_rec[idx] = r;
}

// One gather pass over KCOUNT record groups (compile-time unrolled).
template<int KCOUNT>
__device__ __forceinline__ void gather_cam(const uint2* __restrict__ rp,
                                           const __half2* __restrict__ sp,
                                           int tid, float* acc) {
#pragma unroll
    for (int k = 0; k < KCOUNT; ++k) {
        int i = k * THREADS + tid;
        uint2 r = __ldg(rp + i);
        unsigned int off = r.x & 0xFFFFu;
        __half2 t2  = __half2half2(__ushort_as_half((unsigned short)(r.x >> 16)));
        __half2 v01 = *reinterpret_cast<const __half2*>(&r.y);
        __half2 p0  = sp[off];        // (hm[y0][x0], hm[y0][x1])
        __half2 p1  = sp[off + WW];   // (hm[y1][x0], hm[y1][x1])
        __half2 pl  = __hfma2(__hsub2(p1, p0), t2, p0);   // row lerp
        __half2 pr  = __hmul2(pl, v01);                    // x weights
        float2 f    = __half22float2(pr);
        acc[k] += f.x + f.y;          // fp32 accumulation across cams
    }
}

__global__ __launch_bounds__(THREADS, 1)
void sample_kernel(const float* __restrict__ heatmaps,
                   float* __restrict__ out) {
    // Padded pair-heatmap: (HH+1) rows x WW pairs of fp16. 123,840 bytes.
    extern __shared__ __half2 sp[];

    const int tid = threadIdx.x;
    const int t   = blockIdx.x;

    // Task decode. Full tasks: t < 592 -> chunk_global = t, 25600 bins.
    // Minis: t >= 592 -> chunk_global = 592 + (t-592)/5, sub = (t-592)%5,
    // 5120 bins at offset sub*MCHUNK within the chunk.
    int cg, base, full;
    if (t < NFULL) {
        cg   = t;
        base = (cg % 5) * CHUNK;
        full = 1;
    } else {
        int m = t - NFULL;
        cg   = NFULL + m / 5;
        base = (cg % 5) * CHUNK + (m % 5) * MCHUNK;
        full = 0;
    }
    const int b = cg / 75;
    const int j = (cg % 75) / 5;

    // Zero the pad row (row HH) once.
    if (tid < WW) sp[HMPIX + tid] = __floats2half2_rn(0.f, 0.f);

    // Fill-loop x coordinate (first pixel of this thread's float4).
    // delta = (THREADS*4) % WW = 16.
    const int xstart = (tid * 4) % WW;

    float acc[BPT];
#pragma unroll
    for (int k = 0; k < BPT; ++k) acc[k] = 0.f;

    for (int cam = 0; cam < NC; ++cam) {
        __syncthreads();  // previous gathers done (pad row visible, iter 0)

        // Build fp16 x-pair heatmap in smem (LDG.128 + shfl + STS.128).
        const float*  hm  = heatmaps + (((size_t)b * NC + cam) * NJ + j) * (size_t)HMPIX;
        const float4* hm4 = reinterpret_cast<const float4*>(hm);
        int x = xstart;
#pragma unroll 6
        for (int q = tid; q < HMPIX / 4; q += THREADS) {
            float4 v = __ldg(hm4 + q);
            float vn = __shfl_down_sync(0xffffffffu, v.x, 1);
            if ((tid & 31) == 31 && x != WW - 4)
                vn = __ldg(reinterpret_cast<const float*>(hm4 + q + 1));
            if (x == WW - 4) vn = 0.f;   // pair (239, OOB) -> zero

            __half2 h0 = __floats2half2_rn(v.x, v.y);
            __half2 h1 = __floats2half2_rn(v.y, v.z);
            __half2 h2 = __floats2half2_rn(v.z, v.w);
            __half2 h3 = __floats2half2_rn(v.w, vn);
            uint4 pk;
            pk.x = *reinterpret_cast<unsigned int*>(&h0);
            pk.y = *reinterpret_cast<unsigned int*>(&h1);
            pk.z = *reinterpret_cast<unsigned int*>(&h2);
            pk.w = *reinterpret_cast<unsigned int*>(&h3);
            *reinterpret_cast<uint4*>(sp + q * 4) = pk;

            x += 16;
            if (x >= WW) x -= WW;
        }
        __syncthreads();

        const uint2* __restrict__ rp = g_rec + cam * NB + base;
        if (full) gather_cam<BPT >(rp, sp, tid, acc);
        else      gather_cam<MBPT>(rp, sp, tid, acc);
    }

    float* o = out + ((size_t)(b * NJ + j)) * NB + base;
    const int kmax = full ? BPT : MBPT;
#pragma unroll
    for (int k = 0; k < BPT; ++k) {
        if (k < kmax) {
            float v = acc[k] * 0.2f;                          // mean over 5 cams
            o[k * THREADS + tid] = fminf(fmaxf(v, 0.f), 1.f); // clip [0,1]
        }
    }
}

extern "C" void kernel_launch(void* const* d_in, const int* in_sizes, int n_in,
                              void* d_out, int out_size) {
    const float* heatmaps = (const float*)d_in[0];
    const float* grid     = (const float*)d_in[1];
    if (n_in >= 2 && in_sizes[0] == NC * NB * 2) {
        grid     = (const float*)d_in[0];
        heatmaps = (const float*)d_in[1];
    }

    const int smem_bytes = (HH + 1) * WW * (int)sizeof(__half2);  // 123,840 B
    cudaFuncSetAttribute(sample_kernel,
                         cudaFuncAttributeMaxDynamicSharedMemorySize, smem_bytes);

    prep_kernel<<<(NC * NB + 255) / 256, 256>>>(grid);

    sample_kernel<<<NTASK, THREADS, smem_bytes>>>(heatmaps, (float*)d_out);
}